// round 5
// baseline (speedup 1.0000x reference)
#include <cuda_runtime.h>

#define DD 64
#define HH 512
#define WW 512
#define W4 (WW / 4)
#define THRESH 0.5f

// 64 MB scratch (device global, allocation-free rule): W+H pooled volume
__device__ float4 g_tmp[(size_t)DD * HH * W4];

#define TH1 19   // H rows per block in k1 -> 27 trips, fully unrolled
#define GY1 27   // ceil(512/19)
#define DSEG 16  // D outputs per thread in k2 -> 24 trips

__device__ __forceinline__ float4 vmax4(float4 a, float4 b) {
    return make_float4(fmaxf(a.x, b.x), fmaxf(a.y, b.y),
                       fmaxf(a.z, b.z), fmaxf(a.w, b.w));
}

// ---------------------------------------------------------------------------
// k1: threshold-deferred 9-tap max along W (prefix/suffix from 3 float4 loads)
// then 9-tap max along H via log-window pipeline:
//   M2[j-1]=max(y[j-1],y[j]); M4[j-3]=max(M2[j-3],M2[j-1]);
//   M8[j-7]=max(M4[j-7],M4[j-3]); out[j-4]=max(M8[j-8], y[j]).
// Shift registers + full unroll => renaming only. Zero init = exact 0-padding
// (raw values >= 0 so thresh/maxpool commute with 0-pad).
// ---------------------------------------------------------------------------
__global__ void __launch_bounds__(128) k_wh(const float4* __restrict__ in) {
    const int t  = threadIdx.x;
    const int h0 = blockIdx.y * TH1;
    const int d  = blockIdx.z;
    const float4* base = in    + (size_t)d * HH * W4;
    float4*       tmpb = g_tmp + (size_t)d * HH * W4;

    const float4 z4 = make_float4(0.f, 0.f, 0.f, 0.f);
    float4 y1 = z4;                              // y[j-1]
    float4 m2d2 = z4, m2d1 = z4;                 // M2[j-3], M2[j-2]
    float4 m4d4 = z4, m4d3 = z4, m4d2 = z4, m4d1 = z4;  // M4[j-7..j-4]
    float4 m8p = z4;                             // M8[j-8]

#pragma unroll
    for (int hh = 0; hh < TH1 + 8; hh++) {
        const int hi = h0 - 4 + hh;              // cursor row j
        const bool rowok = (hi >= 0) & (hi < HH);
        const float4* row = base + (size_t)hi * W4;

        float4 L = (rowok && t > 0)      ? row[t - 1] : z4;
        float4 M = rowok                 ? row[t]     : z4;
        float4 R = (rowok && t < W4 - 1) ? row[t + 1] : z4;

        // 9-tap W max: a0..a11 = L.xyzw M.xyzw R.xyzw, out_i = max(a[i..i+8])
        float c = fmaxf(fmaxf(fmaxf(L.w, M.x), fmaxf(M.y, M.z)),
                        fmaxf(M.w, R.x));        // max(a3..a8)
        float4 y;
        y.x = fmaxf(fmaxf(c, L.x), fmaxf(L.y, L.z));
        y.y = fmaxf(fmaxf(c, L.y), fmaxf(L.z, R.y));
        y.z = fmaxf(fmaxf(c, L.z), fmaxf(R.y, R.z));
        y.w = fmaxf(fmaxf(c, R.y), fmaxf(R.z, R.w));

        // emit out row (hi-4) = max(M8[j-8], y[j])
        if (hh >= 8) {
            const int ho = hi - 4;
            if (ho < HH)
                tmpb[(size_t)ho * W4 + t] = vmax4(m8p, y);
        }

        // pipeline update
        float4 m2n = vmax4(y1, y);        // M2[j-1]
        float4 m4n = vmax4(m2d2, m2n);    // M4[j-3] = max(M2[j-3], M2[j-1])
        m8p = vmax4(m4d4, m4n);           // M8[j-7] -> is M8[(j+1)-8] next trip

        y1 = y;
        m2d2 = m2d1; m2d1 = m2n;
        m4d4 = m4d3; m4d3 = m4d2; m4d2 = m4d1; m4d1 = m4n;
    }
}

// ---------------------------------------------------------------------------
// k2: 9-tap max along D via the same log-window pipeline + strict-local-max
// gate. Each thread owns one float4 column, DSEG output planes (+-4 halo).
// grid: (HH*W4/128, DD/DSEG). __ldcs/__stcs keep L2 for the tmp volume.
// ---------------------------------------------------------------------------
__global__ void __launch_bounds__(128) k_d(const float4* __restrict__ in,
                                           float4* __restrict__ out) {
    const size_t col   = (size_t)blockIdx.x * 128 + threadIdx.x;
    const int    d0    = blockIdx.y * DSEG;
    const size_t slice = (size_t)HH * W4;

    const float4 z4 = make_float4(0.f, 0.f, 0.f, 0.f);
    float4 p1 = z4;                              // p[j-1]
    float4 m2d2 = z4, m2d1 = z4;
    float4 m4d4 = z4, m4d3 = z4, m4d2 = z4, m4d1 = z4;
    float4 m8p = z4;                             // M8[j-8]

#pragma unroll
    for (int di = 0; di < DSEG + 8; di++) {
        const int j = d0 + di - 4;               // cursor plane
        float4 p = z4;
        if ((unsigned)j < DD) p = g_tmp[(size_t)j * slice + col];

        if (di >= 8) {                           // out plane o = j-4 in [d0, d0+DSEG)
            const int o = j - 4;
            float4 m = vmax4(m8p, p);            // window max over planes [o-4, o+4]
            const size_t idx = (size_t)o * slice + col;
            const float4 x = __ldcs(&in[idx]);
            float4 ov;
            ov.x = (m.x > THRESH && m.x == x.x) ? m.x : 0.f;
            ov.y = (m.y > THRESH && m.y == x.y) ? m.y : 0.f;
            ov.z = (m.z > THRESH && m.z == x.z) ? m.z : 0.f;
            ov.w = (m.w > THRESH && m.w == x.w) ? m.w : 0.f;
            __stcs(&out[idx], ov);
        }

        float4 m2n = vmax4(p1, p);
        float4 m4n = vmax4(m2d2, m2n);
        m8p = vmax4(m4d4, m4n);

        p1 = p;
        m2d2 = m2d1; m2d1 = m2n;
        m4d4 = m4d3; m4d3 = m4d2; m4d2 = m4d1; m4d1 = m4n;
    }
}

extern "C" void kernel_launch(void* const* d_in, const int* in_sizes, int n_in,
                              void* d_out, int out_size) {
    const float4* in  = (const float4*)d_in[0];
    float4*       out = (float4*)d_out;

    dim3 g1(1, GY1, DD);                 // 1728 blocks
    k_wh<<<g1, 128>>>(in);

    dim3 g2((HH * W4) / 128, DD / DSEG); // 2048 blocks
    k_d<<<g2, 128>>>(in, out);
}

// round 6
// speedup vs baseline: 1.0492x; 1.0492x over previous
#include <cuda_runtime.h>

#define DD 64
#define HH 512
#define WW 512
#define W4 (WW / 4)
#define THRESH 0.5f

// 64 MB scratch (device global, allocation-free rule): W+H pooled volume,
// with sign bit = "center raw value equals its 9x9 WH-window max" flag.
__device__ float4 g_tmp[(size_t)DD * HH * W4];

#define TH1 19   // H rows per block in k1 -> 27 trips (multiple of 9)
#define GY1 27   // ceil(512/19)
#define DSEG 16  // D outputs per thread in k2 -> 24 trips

// ---------------------------------------------------------------------------
// k1: 9-tap max along W then H of the RAW input (threshold deferred; raw
// values >= 0 so 0-padding is exact). Also computes, per output element, the
// flag (whmax == raw center) and packs it into the sign bit of the stored
// value. Mod-9 register ring under unroll-9 => renaming only; no smem/syncs.
// ---------------------------------------------------------------------------
__global__ void __launch_bounds__(128) k_wh(const float4* __restrict__ in) {
    const int t  = threadIdx.x;           // float4 index in row, 0..127
    const int h0 = blockIdx.y * TH1;
    const int d  = blockIdx.z;
    const float4* base = in    + (size_t)d * HH * W4;
    float4*       tmpb = g_tmp + (size_t)d * HH * W4;

    const float4 z4 = make_float4(0.f, 0.f, 0.f, 0.f);
    float4 ring[9];    // W-maxed rows
    float4 cen[9];     // raw center values of those rows

#pragma unroll 9
    for (int hh = 0; hh < TH1 + 8; hh++) {   // 27 trips
        const int hi = h0 - 4 + hh;
        const bool rowok = (hi >= 0) & (hi < HH);
        const float4* row = base + (size_t)hi * W4;

        float4 L = (rowok && t > 0)      ? row[t - 1] : z4;
        float4 M = rowok                 ? row[t]     : z4;
        float4 R = (rowok && t < W4 - 1) ? row[t + 1] : z4;

        // a0..a11 = L.xyzw M.xyzw R.xyzw ; output i = max(a[i..i+8])
        float c = fmaxf(fmaxf(fmaxf(L.w, M.x), fmaxf(M.y, M.z)),
                        fmaxf(M.w, R.x));                  // max(a3..a8)
        float4 y;
        y.x = fmaxf(fmaxf(c, L.x), fmaxf(L.y, L.z));
        y.y = fmaxf(fmaxf(c, L.y), fmaxf(L.z, R.y));
        y.z = fmaxf(fmaxf(c, L.z), fmaxf(R.y, R.z));
        y.w = fmaxf(fmaxf(c, R.y), fmaxf(R.z, R.w));

        ring[hh % 9] = y;
        cen[hh % 9]  = M;                  // raw center row

        const int ho = h0 + hh - 8;        // output row (cursor - 4)
        if (hh >= 8 && ho < HH) {
            float4 m = ring[0];
#pragma unroll
            for (int i = 1; i < 9; i++) {
                m.x = fmaxf(m.x, ring[i].x);
                m.y = fmaxf(m.y, ring[i].y);
                m.z = fmaxf(m.z, ring[i].z);
                m.w = fmaxf(m.w, ring[i].w);
            }
            // center row of the 9-window = cursor-4 = slot (hh-4)%9
            const float4 xc = cen[(hh - 4) % 9];
            float4 o;
            o.x = __uint_as_float(__float_as_uint(m.x) | ((m.x == xc.x) ? 0x80000000u : 0u));
            o.y = __uint_as_float(__float_as_uint(m.y) | ((m.y == xc.y) ? 0x80000000u : 0u));
            o.z = __uint_as_float(__float_as_uint(m.z) | ((m.z == xc.z) ? 0x80000000u : 0u));
            o.w = __uint_as_float(__float_as_uint(m.w) | ((m.w == xc.w) ? 0x80000000u : 0u));
            tmpb[(size_t)ho * W4 + t] = o;
        }
    }
}

// ---------------------------------------------------------------------------
// k2: 9-tap max along D over |tmp| (abs folds into FMNMX input modifiers),
// gate = (M > 0.5 && M == |center| && signbit(center)). No input re-read.
// Ring zero-init = exact 0-padding for out-of-range D. Full unroll => static
// ring indices. grid: (HH*W4/128, DD/DSEG), block 128.
// ---------------------------------------------------------------------------
__global__ void __launch_bounds__(128) k_d(float4* __restrict__ out) {
    const size_t col   = (size_t)blockIdx.x * 128 + threadIdx.x;
    const int    d0    = blockIdx.y * DSEG;
    const size_t slice = (size_t)HH * W4;

    const float4 z4 = make_float4(0.f, 0.f, 0.f, 0.f);
    float4 ring[9];
#pragma unroll
    for (int i = 0; i < 9; i++) ring[i] = z4;

#pragma unroll
    for (int di = 0; di < DSEG + 8; di++) {     // 24 trips, fully unrolled
        const int p = d0 + di - 4;              // plane being loaded
        float4 v = z4;
        if ((unsigned)p < DD) v = g_tmp[(size_t)p * slice + col];
        ring[di % 9] = v;

        const int o = di - 8;                   // output lags cursor by 4
        if (o >= 0) {                           // o in [0, DSEG)
            float4 m = make_float4(fabsf(ring[0].x), fabsf(ring[0].y),
                                   fabsf(ring[0].z), fabsf(ring[0].w));
#pragma unroll
            for (int i = 1; i < 9; i++) {
                m.x = fmaxf(m.x, fabsf(ring[i].x));
                m.y = fmaxf(m.y, fabsf(ring[i].y));
                m.z = fmaxf(m.z, fabsf(ring[i].z));
                m.w = fmaxf(m.w, fabsf(ring[i].w));
            }
            // center plane = cursor-4 = slot (di-4)%9 (static per unroll)
            const float4 cv = ring[(di - 4) % 9];
            float4 ov;
            ov.x = (m.x > THRESH && m.x == fabsf(cv.x) &&
                    (__float_as_uint(cv.x) & 0x80000000u)) ? m.x : 0.f;
            ov.y = (m.y > THRESH && m.y == fabsf(cv.y) &&
                    (__float_as_uint(cv.y) & 0x80000000u)) ? m.y : 0.f;
            ov.z = (m.z > THRESH && m.z == fabsf(cv.z) &&
                    (__float_as_uint(cv.z) & 0x80000000u)) ? m.z : 0.f;
            ov.w = (m.w > THRESH && m.w == fabsf(cv.w) &&
                    (__float_as_uint(cv.w) & 0x80000000u)) ? m.w : 0.f;
            out[(size_t)(d0 + o) * slice + col] = ov;
        }
    }
}

extern "C" void kernel_launch(void* const* d_in, const int* in_sizes, int n_in,
                              void* d_out, int out_size) {
    const float4* in  = (const float4*)d_in[0];
    float4*       out = (float4*)d_out;

    dim3 g1(1, GY1, DD);                 // (1, 27, 64) = 1728 blocks
    k_wh<<<g1, 128>>>(in);

    dim3 g2((HH * W4) / 128, DD / DSEG); // (512, 4) = 2048 blocks
    k_d<<<g2, 128>>>(out);
}

// round 7
// speedup vs baseline: 1.1721x; 1.1172x over previous
#include <cuda_runtime.h>

#define DD 64
#define HH 512
#define WW 512
#define W4 (WW / 4)
#define THRESH 0.5f

// 64 MB scratch (device global, allocation-free rule): W+H pooled volume,
// sign bit = "raw center equals its 9x9 WH-window max" flag.
__device__ float4 g_tmp[(size_t)DD * HH * W4];

#define TH1 19   // H rows per block in k1 -> 27 trips, FULLY unrolled
#define GY1 27   // ceil(512/19)
#define DSEG 16  // D outputs per thread in k2 -> 24 trips

// ---------------------------------------------------------------------------
// k1: 9-tap max along W then H of the RAW input (threshold deferred; raw
// values >= 0 so 0-padding is exact). Sign bit of stored value = flag
// (whmax == raw center). y-ring: mod-9 static under full unroll. Raw-center
// delay: 4-stage shift chain (renamed under full unroll). No smem/syncs.
// ---------------------------------------------------------------------------
__global__ void __launch_bounds__(128) k_wh(const float4* __restrict__ in) {
    const int t  = threadIdx.x;           // float4 index in row, 0..127
    const int h0 = blockIdx.y * TH1;
    const int d  = blockIdx.z;
    const float4* base = in    + (size_t)d * HH * W4;
    float4*       tmpb = g_tmp + (size_t)d * HH * W4;

    const float4 z4 = make_float4(0.f, 0.f, 0.f, 0.f);
    float4 ring[9];                                   // W-maxed rows
    float4 c0 = z4, c1 = z4, c2 = z4, c3 = z4;        // raw-center delay chain

#pragma unroll
    for (int hh = 0; hh < TH1 + 8; hh++) {   // 27 trips, fully unrolled
        const int hi = h0 - 4 + hh;
        const bool rowok = (hi >= 0) & (hi < HH);
        const float4* row = base + (size_t)hi * W4;

        float4 L = (rowok && t > 0)      ? row[t - 1] : z4;
        float4 M = rowok                 ? row[t]     : z4;
        float4 R = (rowok && t < W4 - 1) ? row[t + 1] : z4;

        // a0..a11 = L.xyzw M.xyzw R.xyzw ; output i = max(a[i..i+8])
        float c  = fmaxf(fmaxf(fmaxf(L.w, M.x), fmaxf(M.y, M.z)),
                         fmaxf(M.w, R.x));             // max(a3..a8)
        float t1 = fmaxf(L.y, L.z);                    // max(a1,a2)
        float t2 = fmaxf(R.y, R.z);                    // max(a9,a10)
        float4 y;
        y.x = fmaxf(fmaxf(c, L.x), t1);
        y.y = fmaxf(fmaxf(c, R.y), t1);
        y.z = fmaxf(fmaxf(c, L.z), t2);
        y.w = fmaxf(fmaxf(c, R.w), t2);

        ring[hh % 9] = y;                 // static index (full unroll)

        const int ho = h0 + hh - 8;       // output row (cursor - 4)
        if (hh >= 8 && ho < HH) {
            float4 m = ring[0];
#pragma unroll
            for (int i = 1; i < 9; i++) {
                m.x = fmaxf(m.x, ring[i].x);
                m.y = fmaxf(m.y, ring[i].y);
                m.z = fmaxf(m.z, ring[i].z);
                m.w = fmaxf(m.w, ring[i].w);
            }
            // c3 = raw center row from trip hh-4 = row (hi-4) = output row
            float4 o;
            o.x = __uint_as_float(__float_as_uint(m.x) | ((m.x == c3.x) ? 0x80000000u : 0u));
            o.y = __uint_as_float(__float_as_uint(m.y) | ((m.y == c3.y) ? 0x80000000u : 0u));
            o.z = __uint_as_float(__float_as_uint(m.z) | ((m.z == c3.z) ? 0x80000000u : 0u));
            o.w = __uint_as_float(__float_as_uint(m.w) | ((m.w == c3.w) ? 0x80000000u : 0u));
            tmpb[(size_t)ho * W4 + t] = o;
        }

        c3 = c2; c2 = c1; c1 = c0; c0 = M;   // renamed under full unroll
    }
}

// ---------------------------------------------------------------------------
// k2 (unchanged from R6): 9-tap max along D over |tmp|, gate =
// (M > 0.5 && M == |center| && signbit(center)). No input re-read.
// ---------------------------------------------------------------------------
__global__ void __launch_bounds__(128) k_d(float4* __restrict__ out) {
    const size_t col   = (size_t)blockIdx.x * 128 + threadIdx.x;
    const int    d0    = blockIdx.y * DSEG;
    const size_t slice = (size_t)HH * W4;

    const float4 z4 = make_float4(0.f, 0.f, 0.f, 0.f);
    float4 ring[9];
#pragma unroll
    for (int i = 0; i < 9; i++) ring[i] = z4;

#pragma unroll
    for (int di = 0; di < DSEG + 8; di++) {     // 24 trips, fully unrolled
        const int p = d0 + di - 4;              // plane being loaded
        float4 v = z4;
        if ((unsigned)p < DD) v = g_tmp[(size_t)p * slice + col];
        ring[di % 9] = v;

        const int o = di - 8;                   // output lags cursor by 4
        if (o >= 0) {
            float4 m = make_float4(fabsf(ring[0].x), fabsf(ring[0].y),
                                   fabsf(ring[0].z), fabsf(ring[0].w));
#pragma unroll
            for (int i = 1; i < 9; i++) {
                m.x = fmaxf(m.x, fabsf(ring[i].x));
                m.y = fmaxf(m.y, fabsf(ring[i].y));
                m.z = fmaxf(m.z, fabsf(ring[i].z));
                m.w = fmaxf(m.w, fabsf(ring[i].w));
            }
            const float4 cv = ring[(di - 4) % 9];   // center plane (static)
            float4 ov;
            ov.x = (m.x > THRESH && m.x == fabsf(cv.x) &&
                    (__float_as_uint(cv.x) & 0x80000000u)) ? m.x : 0.f;
            ov.y = (m.y > THRESH && m.y == fabsf(cv.y) &&
                    (__float_as_uint(cv.y) & 0x80000000u)) ? m.y : 0.f;
            ov.z = (m.z > THRESH && m.z == fabsf(cv.z) &&
                    (__float_as_uint(cv.z) & 0x80000000u)) ? m.z : 0.f;
            ov.w = (m.w > THRESH && m.w == fabsf(cv.w) &&
                    (__float_as_uint(cv.w) & 0x80000000u)) ? m.w : 0.f;
            out[(size_t)(d0 + o) * slice + col] = ov;
        }
    }
}

extern "C" void kernel_launch(void* const* d_in, const int* in_sizes, int n_in,
                              void* d_out, int out_size) {
    const float4* in  = (const float4*)d_in[0];
    float4*       out = (float4*)d_out;

    dim3 g1(1, GY1, DD);                 // (1, 27, 64) = 1728 blocks
    k_wh<<<g1, 128>>>(in);

    dim3 g2((HH * W4) / 128, DD / DSEG); // (512, 4) = 2048 blocks
    k_d<<<g2, 128>>>(out);
}